// round 3
// baseline (speedup 1.0000x reference)
#include <cuda_runtime.h>
#include <cstdint>
#include <math.h>

#define B_SZ 4
#define S_LEN 4096
#define E_SZ 768
#define H_SZ 64

typedef unsigned long long u64;

// Scratch: Q,K natural [b][s][h]; V transposed [b][h][s].
__device__ float g_q [B_SZ * S_LEN * H_SZ];
__device__ float g_k [B_SZ * S_LEN * H_SZ];
__device__ float g_vt[B_SZ * H_SZ * S_LEN];

// ---- packed fp32 helpers -------------------------------------------------
__device__ __forceinline__ void fma2(u64 &acc, double a, double b) {
    asm("fma.rn.f32x2 %0, %1, %2, %0;"
        : "+l"(acc)
        : "l"(__double_as_longlong(a)), "l"(__double_as_longlong(b)));
}
__device__ __forceinline__ u64 dup2(float v) {
    u64 r; asm("mov.b64 %0, {%1,%1};" : "=l"(r) : "f"(v)); return r;
}
__device__ __forceinline__ void mul2(u64 &acc, u64 s) {
    asm("mul.rn.f32x2 %0, %0, %1;" : "+l"(acc) : "l"(s));
}
__device__ __forceinline__ float2 unpack2(u64 v) {
    float2 f; asm("mov.b64 {%0,%1}, %2;" : "=f"(f.x), "=f"(f.y) : "l"(v)); return f;
}
__device__ __forceinline__ void cp16(uint32_t dst, const float* src) {
    asm volatile("cp.async.cg.shared.global [%0], [%1], 16;" :: "r"(dst), "l"(src));
}

// ---------------------------------------------------------------------------
// Kernel 1: QKV projection. grid=(128,3), 256 thr, >=2 CTAs/SM.
// C[s][h] = sum_e x[s][e] W[h][e].  BM=128, BN=64, BK=32; tile 8x4; f32x2 on E.
// ---------------------------------------------------------------------------
__global__ __launch_bounds__(256, 2) void qkv_kernel(
    const float* __restrict__ x,
    const float* __restrict__ Wq,
    const float* __restrict__ Wk,
    const float* __restrict__ Wv)
{
    const int wsel = blockIdx.y;
    const float* __restrict__ W = (wsel == 0) ? Wq : (wsel == 1) ? Wk : Wv;

    __shared__ float xs[128 * 36];
    __shared__ float ws[64 * 36];

    const int tid = threadIdx.x;
    const int tx = tid & 15;     // h cols: tx + 16j
    const int ty = tid >> 4;     // s rows: 8ty + i
    const int rowBase = blockIdx.x * 128;

    u64 acc[8][4];
#pragma unroll
    for (int i = 0; i < 8; i++)
#pragma unroll
        for (int j = 0; j < 4; j++) acc[i][j] = 0ull;

    for (int kb = 0; kb < E_SZ; kb += 32) {
#pragma unroll
        for (int p = 0; p < 4; p++) {
            int f = p * 256 + tid;
            int r = f >> 3, c = f & 7;
            *reinterpret_cast<float4*>(&xs[r * 36 + 4 * c]) =
                *reinterpret_cast<const float4*>(&x[(size_t)(rowBase + r) * E_SZ + kb + 4 * c]);
        }
#pragma unroll
        for (int p = 0; p < 2; p++) {
            int f = p * 256 + tid;
            int r = f >> 3, c = f & 7;
            *reinterpret_cast<float4*>(&ws[r * 36 + 4 * c]) =
                *reinterpret_cast<const float4*>(&W[(size_t)r * E_SZ + kb + 4 * c]);
        }
        __syncthreads();
#pragma unroll 2
        for (int c = 0; c < 8; c++) {
            double2 xd[8], wd[4];
#pragma unroll
            for (int i = 0; i < 8; i++)
                xd[i] = *reinterpret_cast<const double2*>(&xs[(8 * ty + i) * 36 + 4 * c]);
#pragma unroll
            for (int j = 0; j < 4; j++)
                wd[j] = *reinterpret_cast<const double2*>(&ws[(tx + 16 * j) * 36 + 4 * c]);
#pragma unroll
            for (int i = 0; i < 8; i++)
#pragma unroll
                for (int j = 0; j < 4; j++) {
                    fma2(acc[i][j], xd[i].x, wd[j].x);
                    fma2(acc[i][j], xd[i].y, wd[j].y);
                }
        }
        __syncthreads();
    }

    float r_[8][4];
#pragma unroll
    for (int i = 0; i < 8; i++)
#pragma unroll
        for (int j = 0; j < 4; j++) {
            float2 f = unpack2(acc[i][j]);
            r_[i][j] = f.x + f.y;
        }

    const int b = rowBase >> 12;
    const int s0 = rowBase & 4095;
    if (wsel < 2) {
        float* dst = (wsel == 0) ? g_q : g_k;
#pragma unroll
        for (int i = 0; i < 8; i++)
#pragma unroll
            for (int j = 0; j < 4; j++)
                dst[(size_t)(b * S_LEN + s0 + 8 * ty + i) * H_SZ + tx + 16 * j] = r_[i][j];
    } else {
        // V transposed: g_vt[b][h][s]
#pragma unroll
        for (int j = 0; j < 4; j++) {
            int h = tx + 16 * j;
            float* dst = &g_vt[(size_t)(b * H_SZ + h) * S_LEN + s0 + 8 * ty];
            *reinterpret_cast<float4*>(dst) = make_float4(r_[0][j], r_[1][j], r_[2][j], r_[3][j]);
            *reinterpret_cast<float4*>(dst + 4) = make_float4(r_[4][j], r_[5][j], r_[6][j], r_[7][j]);
        }
    }
}

// ---------------------------------------------------------------------------
// Kernel 2: flash attention, floor(QK^T/8), f32x2-packed GEMMs.
// grid=(32,4), 512 thr, thread tile 4x4 (low regs -> 16 warps/SM).
// Smem (floats): Qs[128*68] @0 | Ks[2][64*68] @8704 | Vt[2][64*68] @17408 |
//                Pb[128*68] @26112.  Total 139264 B (dynamic).
// ---------------------------------------------------------------------------
#define QS_OFF 0
#define KS_OFF 8704
#define VT_OFF 17408
#define PB_OFF 26112
#define BUF_STRIDE 4352
#define SMEM_BYTES (34816 * 4)

__global__ __launch_bounds__(512, 1) void flash_kernel(float* __restrict__ out)
{
    extern __shared__ float sm[];
    const int tid = threadIdx.x;
    const int tx = tid & 15;     // k/h col group: cols tx + 16j
    const int ty = tid >> 4;     // q row group: rows 4ty + i   (ty in 0..31)
    const int b = blockIdx.y;
    const int q0 = blockIdx.x * 128;
    const uint32_t smb = (uint32_t)__cvta_generic_to_shared(sm);

    // prologue: async-load tile 0 (K & V)
#pragma unroll
    for (int p = 0; p < 2; p++) {
        int f = p * 512 + tid;
        int r = f >> 4, c = f & 15;
        cp16(smb + (KS_OFF + r * 68 + 4 * c) * 4,
             &g_k[(size_t)(b * S_LEN + r) * H_SZ + 4 * c]);
        cp16(smb + (VT_OFF + r * 68 + 4 * c) * 4,
             &g_vt[(size_t)(b * H_SZ + r) * S_LEN + 4 * c]);
    }
    asm volatile("cp.async.commit_group;");

    // Q tile: plain vector loads
#pragma unroll
    for (int p = 0; p < 4; p++) {
        int f = p * 512 + tid;
        int r = f >> 4, c = f & 15;
        *reinterpret_cast<float4*>(&sm[QS_OFF + r * 68 + 4 * c]) =
            *reinterpret_cast<const float4*>(&g_q[(size_t)(b * S_LEN + q0 + r) * H_SZ + 4 * c]);
    }

    float m[4], l[4];
    u64 o2[4][4];
#pragma unroll
    for (int i = 0; i < 4; i++) {
        m[i] = -1e30f; l[i] = 0.f;
#pragma unroll
        for (int j = 0; j < 4; j++) o2[i][j] = 0ull;
    }

    for (int t = 0; t < S_LEN / 64; t++) {
        __syncthreads();                     // prev PV / P-buffer fully consumed
        if (t + 1 < S_LEN / 64) {
            const int buf = (t + 1) & 1;
            const int k0n = (t + 1) * 64;
#pragma unroll
            for (int p = 0; p < 2; p++) {
                int f = p * 512 + tid;
                int r = f >> 4, c = f & 15;
                cp16(smb + (KS_OFF + buf * BUF_STRIDE + r * 68 + 4 * c) * 4,
                     &g_k[(size_t)(b * S_LEN + k0n + r) * H_SZ + 4 * c]);
                cp16(smb + (VT_OFF + buf * BUF_STRIDE + r * 68 + 4 * c) * 4,
                     &g_vt[(size_t)(b * H_SZ + r) * S_LEN + k0n + 4 * c]);
            }
            asm volatile("cp.async.commit_group;");
            asm volatile("cp.async.wait_group 1;");
        } else {
            asm volatile("cp.async.wait_group 0;");
        }
        __syncthreads();                     // current K/V tile visible

        const float* Ks = sm + KS_OFF + (t & 1) * BUF_STRIDE;
        const float* Vt = sm + VT_OFF + (t & 1) * BUF_STRIDE;
        float* Pb = sm + PB_OFF;

        // ---- S = Q K^T : pack along h (same accumulation order as before)
        u64 acc[4][4];
#pragma unroll
        for (int i = 0; i < 4; i++)
#pragma unroll
            for (int j = 0; j < 4; j++) acc[i][j] = 0ull;

#pragma unroll 4
        for (int c = 0; c < 16; c++) {
            double2 qd[4], kd[4];
#pragma unroll
            for (int i = 0; i < 4; i++)
                qd[i] = *reinterpret_cast<const double2*>(&sm[QS_OFF + (4 * ty + i) * 68 + 4 * c]);
#pragma unroll
            for (int j = 0; j < 4; j++)
                kd[j] = *reinterpret_cast<const double2*>(&Ks[(tx + 16 * j) * 68 + 4 * c]);
#pragma unroll
            for (int i = 0; i < 4; i++)
#pragma unroll
                for (int j = 0; j < 4; j++) {
                    fma2(acc[i][j], qd[i].x, kd[j].x);
                    fma2(acc[i][j], qd[i].y, kd[j].y);
                }
        }

        // ---- floor + online softmax (row reduction over 16 tx lanes)
#pragma unroll
        for (int i = 0; i < 4; i++) {
            float s[4];
            float rm = -1e30f;
#pragma unroll
            for (int j = 0; j < 4; j++) {
                float2 f = unpack2(acc[i][j]);
                s[j] = floorf((f.x + f.y) * 0.125f);
                rm = fmaxf(rm, s[j]);
            }
#pragma unroll
            for (int d = 1; d < 16; d <<= 1)
                rm = fmaxf(rm, __shfl_xor_sync(0xffffffffu, rm, d));
            float mn = fmaxf(m[i], rm);
            float alpha = __expf(m[i] - mn);
            m[i] = mn;
            float pv[4];
            float rs = 0.f;
#pragma unroll
            for (int j = 0; j < 4; j++) {
                pv[j] = __expf(s[j] - mn);
                rs += pv[j];
            }
#pragma unroll
            for (int d = 1; d < 16; d <<= 1)
                rs += __shfl_xor_sync(0xffffffffu, rs, d);
            l[i] = l[i] * alpha + rs;
            u64 a2 = dup2(alpha);
#pragma unroll
            for (int j = 0; j < 4; j++) mul2(o2[i][j], a2);
#pragma unroll
            for (int j = 0; j < 4; j++)
                Pb[(4 * ty + i) * 68 + tx + 16 * j] = pv[j];
        }
        __syncthreads();                     // P tile complete

        // ---- O += P V : pack along k (same order as before)
#pragma unroll 4
        for (int c = 0; c < 16; c++) {
            double2 pd[4], vd[4];
#pragma unroll
            for (int i = 0; i < 4; i++)
                pd[i] = *reinterpret_cast<const double2*>(&Pb[(4 * ty + i) * 68 + 4 * c]);
#pragma unroll
            for (int j = 0; j < 4; j++)
                vd[j] = *reinterpret_cast<const double2*>(&Vt[(tx + 16 * j) * 68 + 4 * c]);
#pragma unroll
            for (int i = 0; i < 4; i++)
#pragma unroll
                for (int j = 0; j < 4; j++) {
                    fma2(o2[i][j], pd[i].x, vd[j].x);
                    fma2(o2[i][j], pd[i].y, vd[j].y);
                }
        }
    }

    // ---- epilogue
#pragma unroll
    for (int i = 0; i < 4; i++) {
        float inv = 1.0f / l[i];
#pragma unroll
        for (int j = 0; j < 4; j++) {
            float2 f = unpack2(o2[i][j]);
            out[(size_t)(b * S_LEN + q0 + 4 * ty + i) * H_SZ + tx + 16 * j] = (f.x + f.y) * inv;
        }
    }
}

// ---------------------------------------------------------------------------
extern "C" void kernel_launch(void* const* d_in, const int* in_sizes, int n_in,
                              void* d_out, int out_size)
{
    const float* x  = (const float*)d_in[0];
    const float* Wq = (const float*)d_in[1];
    const float* Wk = (const float*)d_in[2];
    const float* Wv = (const float*)d_in[3];
    float* out = (float*)d_out;

    cudaFuncSetAttribute(flash_kernel, cudaFuncAttributeMaxDynamicSharedMemorySize, SMEM_BYTES);

    qkv_kernel<<<dim3(128, 3), 256>>>(x, Wq, Wk, Wv);
    flash_kernel<<<dim3(S_LEN / 128, B_SZ), 512, SMEM_BYTES>>>(out);
}